// round 6
// baseline (speedup 1.0000x reference)
#include <cuda_runtime.h>
#include <math.h>

// Problem constants (fixed shapes from reference)
#define Hh   128
#define Ww   256
#define Bn   2
#define COUT 144
#define CIN1 513
#define DSf  4
#define HWsz (Hh*Ww)

// Scratch (device globals: allocation-free per harness rules)
__device__ float g_x0[(size_t)Bn*CIN1*HWsz];   // concat(disp, space_to_depth(fea))
__device__ float g_xa[(size_t)Bn*COUT*HWsz];   // ping
__device__ float g_xb[(size_t)Bn*COUT*HWsz];   // pong

typedef unsigned long long ull;

// ---- packed f32x2 helpers (sm_100+ PTX; SASS FFMA2) -----------------------
__device__ __forceinline__ ull f32x2_pack(float lo, float hi) {
    ull r;
    asm("mov.b64 %0, {%1, %2};" : "=l"(r) : "f"(lo), "f"(hi));
    return r;
}
__device__ __forceinline__ void f32x2_fma(ull& d, ull a, ull b) {
    asm("fma.rn.f32x2 %0, %1, %2, %0;" : "+l"(d) : "l"(a), "l"(b));
}
__device__ __forceinline__ float2 f32x2_unpack(ull v) {
    float2 f;
    asm("mov.b64 {%0, %1}, %2;" : "=f"(f.x), "=f"(f.y) : "l"(v));
    return f;
}

// ---------------------------------------------------------------------------
// Kernel 1: build x0[b, ci, h, w]
//   ci==0               -> disp[b,h,w]
//   ci = 1 + c*16+i*4+j -> left_fea[b, c, h*4+i, w*4+j]
// ---------------------------------------------------------------------------
__global__ void s2d_kernel(const float* __restrict__ disp,
                           const float* __restrict__ fea) {
    size_t idx = (size_t)blockIdx.x * blockDim.x + threadIdx.x;
    size_t total = (size_t)Bn * CIN1 * HWsz;
    if (idx >= total) return;
    int w  = (int)(idx % Ww);
    int h  = (int)((idx / Ww) % Hh);
    int ci = (int)((idx / HWsz) % CIN1);
    int b  = (int)(idx / ((size_t)HWsz * CIN1));
    float v;
    if (ci == 0) {
        v = disp[((size_t)b*Hh + h)*Ww + w];
    } else {
        int r  = ci - 1;
        int c  = r >> 4;
        int ij = r & 15;
        int i  = ij >> 2;
        int j  = ij & 3;
        v = fea[(((size_t)b*32 + c)*(Hh*DSf) + h*DSf + i)*(Ww*DSf) + w*DSf + j];
    }
    g_x0[idx] = v;
}

// ---------------------------------------------------------------------------
// Kernel 2: 3x3 conv (zero pad 1) + BN(eval) + optional ReLU.
// Block: 256 threads. Tile = 16(H) x 32(W) spatial x 24 output channels.
// Thread: 2x4 spatial micro-tile x 6 ocs -> 24 packed f32x2 accumulators.
// Even input pairs loaded as aligned LDS.64; only odd pairs packed.
// Weights staged pre-duplicated as (w,w). Double-buffered smem, ic unroll 2.
// grid = (64 spatial tiles, 6 oc chunks of 24, B)
// ---------------------------------------------------------------------------
#define TILE_H 16
#define TILE_W 32
#define HALO_H 18
#define HALO_W 34
#define SROW   36   // padded row (words): 144B rows keep 16B alignment
#define OCB    24   // output channels per block
#define OCT    6    // output channels per thread

template<int CIN, bool RELU>
__global__ __launch_bounds__(256, 2)
void conv3x3_bn(const float* __restrict__ in,    // [B, CIN, H, W]
                const float* __restrict__ wt,    // [144, CIN, 3, 3]
                const float* __restrict__ gam,   // [144]
                const float* __restrict__ bet,   // [144]
                float* __restrict__ out)         // [B, 144, H, W]
{
    __shared__ float  s_in[2][HALO_H][SROW];
    __shared__ float2 s_wt[2][OCB][9];           // (w, w) duplicated lanes

    const int t    = threadIdx.x;
    const int tile = blockIdx.x;           // 8 tiles in W, 8 in H
    const int tx   = tile & 7;
    const int ty   = tile >> 3;
    const int ocb  = blockIdx.y * OCB;
    const int b    = blockIdx.z;

    const int ocg  = t >> 6;               // 0..3 -> ocs [ocg*6, ocg*6+5]
    const int sp   = t & 63;
    const int sy   = sp >> 3;              // 0..7 -> 2 rows each
    const int sx   = sp & 7;               // 0..7 -> 4 cols each
    const int py   = ty*TILE_H + sy*2;
    const int px   = tx*TILE_W + sx*4;

    const float* inb = in + (size_t)b * CIN * HWsz;
    const float* wtb = wt + (size_t)ocb * CIN * 9;

    // ---- hoisted staging descriptors (loop-invariant across ic)
    // slots s=0,1 always active (t+256 < 612); slot 2 active iff t < 100.
    int  stg_soff[3];
    int  stg_goff[3];
    bool stg_val [3];
    const bool s2_act = (t < HALO_H*HALO_W - 512);
    {
        const int gy0 = ty*TILE_H - 1;
        const int gx0 = tx*TILE_W - 1;
#pragma unroll
        for (int s = 0; s < 3; s++) {
            int l = t + s*256;
            int ly = l / HALO_W, lx = l - ly*HALO_W;
            int gy = gy0 + ly,   gx = gx0 + lx;
            bool val = (s < 2 || s2_act) && gy >= 0 && gy < Hh && gx >= 0 && gx < Ww;
            stg_val[s]  = val;
            stg_soff[s] = ly*SROW + lx;
            stg_goff[s] = val ? (gy*Ww + gx) : 0;
        }
    }
    // weight staging indices (threads 0..215 cover 24 oc x 9 taps)
    const int  woo   = t / 9;
    const int  wkk   = t - woo*9;
    const bool wact  = (t < OCB*9);
    const float* wsrc = wtb + (size_t)woo*CIN*9 + wkk;

    // acc[k][oy][oxp]: oxp=0 -> out cols (0,1), oxp=1 -> (2,3), packed f32x2
    ull acc[OCT][2][2];
#pragma unroll
    for (int k = 0; k < OCT; k++)
#pragma unroll
        for (int oy = 0; oy < 2; oy++) {
            acc[k][oy][0] = 0ull;
            acc[k][oy][1] = 0ull;
        }

    // ---- staging helper: load plane `ic` into buffer `buf`
    auto stage = [&](int ic, int buf) {
        const float* ip = inb + (size_t)ic * HWsz;
        float* sb = &s_in[buf][0][0];
        {
            float v0 = stg_val[0] ? __ldg(ip + stg_goff[0]) : 0.0f;
            float v1 = stg_val[1] ? __ldg(ip + stg_goff[1]) : 0.0f;
            sb[stg_soff[0]] = v0;
            sb[stg_soff[1]] = v1;
        }
        if (s2_act) {
            float v2 = stg_val[2] ? __ldg(ip + stg_goff[2]) : 0.0f;
            sb[stg_soff[2]] = v2;
        }
        if (wact) {
            float w0 = __ldg(wsrc + (size_t)ic*9);
            s_wt[buf][woo][wkk] = make_float2(w0, w0);
        }
    };

    // ---- compute helper: accumulate from buffer `buf`
    auto compute = [&](int buf) {
        // p[r][0..4] = pairs (x0,x1)(x1,x2)(x2,x3)(x3,x4)(x4,x5)
        ull p[4][5];
#pragma unroll
        for (int r = 0; r < 4; r++) {
            const float* rp = &s_in[buf][sy*2 + r][sx*4];
            ull e0 = *(const ull*)(rp + 0);   // (x0,x1) 8B-aligned
            ull e1 = *(const ull*)(rp + 2);   // (x2,x3)
            ull e2 = *(const ull*)(rp + 4);   // (x4,x5)
            float2 f0 = f32x2_unpack(e0);
            float2 f1 = f32x2_unpack(e1);
            float2 f2 = f32x2_unpack(e2);
            p[r][0] = e0;
            p[r][1] = f32x2_pack(f0.y, f1.x);
            p[r][2] = e1;
            p[r][3] = f32x2_pack(f1.y, f2.x);
            p[r][4] = e2;
        }
#pragma unroll
        for (int k = 0; k < OCT; k++) {
            const ull* wp = (const ull*)&s_wt[buf][ocg*OCT + k][0];
            ull wv[9];
#pragma unroll
            for (int q = 0; q < 9; q++) wv[q] = wp[q];   // LDS.64 broadcast
#pragma unroll
            for (int oy = 0; oy < 2; oy++)
#pragma unroll
                for (int dy = 0; dy < 3; dy++) {
                    const int r = oy + dy;
#pragma unroll
                    for (int dx = 0; dx < 3; dx++) {
                        f32x2_fma(acc[k][oy][0], wv[dy*3+dx], p[r][dx]);
                        f32x2_fma(acc[k][oy][1], wv[dy*3+dx], p[r][dx+2]);
                    }
                }
        }
    };

    // ---- pipelined mainloop, ic unrolled by 2 (static buffer indices)
    stage(0, 0);
    __syncthreads();
#pragma unroll 1
    for (int ic = 0; ic < CIN; ic += 2) {
        if (ic + 1 < CIN) stage(ic + 1, 1);
        compute(0);
        __syncthreads();
        if (ic + 1 < CIN) {
            if (ic + 2 < CIN) stage(ic + 2, 0);
            compute(1);
            __syncthreads();
        }
    }

    // --- BN epilogue (+ReLU), vectorized store
    const float inv = rsqrtf(1.0f + 1e-5f);
#pragma unroll
    for (int k = 0; k < OCT; k++) {
        int oc = ocb + ocg*OCT + k;
        float sc = __ldg(gam + oc) * inv;
        float bb = __ldg(bet + oc);
#pragma unroll
        for (int oy = 0; oy < 2; oy++) {
            float2 a01 = f32x2_unpack(acc[k][oy][0]);
            float2 a23 = f32x2_unpack(acc[k][oy][1]);
            float4 v;
            v.x = a01.x * sc + bb;
            v.y = a01.y * sc + bb;
            v.z = a23.x * sc + bb;
            v.w = a23.y * sc + bb;
            if (RELU) {
                v.x = fmaxf(v.x, 0.0f); v.y = fmaxf(v.y, 0.0f);
                v.z = fmaxf(v.z, 0.0f); v.w = fmaxf(v.w, 0.0f);
            }
            *(float4*)(out + ((size_t)b*COUT + oc)*HWsz + (size_t)(py+oy)*Ww + px) = v;
        }
    }
}

// ---------------------------------------------------------------------------
// Kernel 3: per-(b,h,w): 16 softmaxes over 9 logits, blend 3x3 replication-
// padded disparity neighborhood, pixel-shuffle (x4), scale by DS=4.
// ---------------------------------------------------------------------------
__global__ void finalize_kernel(const float* __restrict__ x3,
                                const float* __restrict__ disp,
                                float* __restrict__ out) {
    int idx = blockIdx.x * blockDim.x + threadIdx.x;   // Bn*HWsz
    if (idx >= Bn*HWsz) return;
    int w = idx % Ww;
    int h = (idx / Ww) % Hh;
    int b = idx / HWsz;

    // 3x3 neighborhood with edge clamp (ReplicationPad2d(1))
    float nb[9];
#pragma unroll
    for (int dy = 0; dy < 3; dy++) {
        int hh = min(max(h + dy - 1, 0), Hh-1);
#pragma unroll
        for (int dx = 0; dx < 3; dx++) {
            int ww = min(max(w + dx - 1, 0), Ww-1);
            nb[dy*3+dx] = __ldg(disp + ((size_t)b*Hh + hh)*Ww + ww);
        }
    }

    const float* xp = x3 + (size_t)b*COUT*HWsz + (size_t)h*Ww + w;
    float* ob = out + (size_t)b*(Hh*DSf)*(Ww*DSf);

#pragma unroll
    for (int ds = 0; ds < 16; ds++) {
        float v[9];
        float mx = -3.4e38f;
#pragma unroll
        for (int k = 0; k < 9; k++) {
            v[k] = __ldg(xp + (size_t)(ds*9 + k)*HWsz);
            mx = fmaxf(mx, v[k]);
        }
        float se = 0.0f, r = 0.0f;
#pragma unroll
        for (int k = 0; k < 9; k++) {
            float e = expf(v[k] - mx);
            se += e;
            r = fmaf(e, nb[k], r);
        }
        r = r / se * (float)DSf;
        int i = ds >> 2, j = ds & 3;
        ob[(size_t)(h*DSf + i)*(Ww*DSf) + (size_t)w*DSf + j] = r;
    }
}

// ---------------------------------------------------------------------------
extern "C" void kernel_launch(void* const* d_in, const int* in_sizes, int n_in,
                              void* d_out, int out_size) {
    (void)in_sizes; (void)n_in; (void)out_size;
    const float* disp = (const float*)d_in[0];
    const float* fea  = (const float*)d_in[1];
    const float* w1   = (const float*)d_in[2];
    const float* g1   = (const float*)d_in[3];
    const float* b1   = (const float*)d_in[4];
    const float* w2   = (const float*)d_in[5];
    const float* g2   = (const float*)d_in[6];
    const float* b2   = (const float*)d_in[7];
    const float* w3   = (const float*)d_in[8];
    const float* g3   = (const float*)d_in[9];
    const float* b3   = (const float*)d_in[10];
    float* out = (float*)d_out;

    float *x0, *xa, *xb;
    cudaGetSymbolAddress((void**)&x0, g_x0);
    cudaGetSymbolAddress((void**)&xa, g_xa);
    cudaGetSymbolAddress((void**)&xb, g_xb);

    // 1) space-to-depth + concat
    {
        size_t n0 = (size_t)Bn*CIN1*HWsz;
        s2d_kernel<<<(unsigned)((n0 + 255)/256), 256>>>(disp, fea);
    }

    // 2) three convs (ping-pong xa/xb)
    dim3 grid(64, COUT/OCB, Bn);   // 64 spatial tiles, 6 oc chunks of 24, batch
    conv3x3_bn<CIN1, true ><<<grid, 256>>>(x0, w1, g1, b1, xa);
    conv3x3_bn<COUT, true ><<<grid, 256>>>(xa, w2, g2, b2, xb);
    conv3x3_bn<COUT, false><<<grid, 256>>>(xb, w3, g3, b3, xa);

    // 3) softmax + disparity blend + pixel shuffle
    finalize_kernel<<<(Bn*HWsz + 127)/128, 128>>>(xa, disp, out);
}

// round 8
// speedup vs baseline: 1.1260x; 1.1260x over previous
#include <cuda_runtime.h>
#include <math.h>

// Problem constants (fixed shapes from reference)
#define Hh   128
#define Ww   256
#define Bn   2
#define COUT 144
#define CIN1 513
#define DSf  4
#define HWsz (Hh*Ww)

// Scratch (device globals: allocation-free per harness rules)
__device__ float g_x0[(size_t)Bn*CIN1*HWsz];   // concat(disp, space_to_depth(fea))
__device__ float g_xa[(size_t)Bn*COUT*HWsz];   // ping
__device__ float g_xb[(size_t)Bn*COUT*HWsz];   // pong

typedef unsigned long long ull;

// ---- packed f32x2 helpers (sm_100+ PTX; SASS FFMA2) -----------------------
__device__ __forceinline__ ull f32x2_pack(float lo, float hi) {
    ull r;
    asm("mov.b64 %0, {%1, %2};" : "=l"(r) : "f"(lo), "f"(hi));
    return r;
}
__device__ __forceinline__ void f32x2_fma(ull& d, ull a, ull b) {
    asm("fma.rn.f32x2 %0, %1, %2, %0;" : "+l"(d) : "l"(a), "l"(b));
}
__device__ __forceinline__ float2 f32x2_unpack(ull v) {
    float2 f;
    asm("mov.b64 {%0, %1}, %2;" : "=f"(f.x), "=f"(f.y) : "l"(v));
    return f;
}

// ---------------------------------------------------------------------------
// Kernel 1: build x0[b, ci, h, w]
//   ci==0               -> disp[b,h,w]
//   ci = 1 + c*16+i*4+j -> left_fea[b, c, h*4+i, w*4+j]
// ---------------------------------------------------------------------------
__global__ void s2d_kernel(const float* __restrict__ disp,
                           const float* __restrict__ fea) {
    size_t idx = (size_t)blockIdx.x * blockDim.x + threadIdx.x;
    size_t total = (size_t)Bn * CIN1 * HWsz;
    if (idx >= total) return;
    int w  = (int)(idx % Ww);
    int h  = (int)((idx / Ww) % Hh);
    int ci = (int)((idx / HWsz) % CIN1);
    int b  = (int)(idx / ((size_t)HWsz * CIN1));
    float v;
    if (ci == 0) {
        v = disp[((size_t)b*Hh + h)*Ww + w];
    } else {
        int r  = ci - 1;
        int c  = r >> 4;
        int ij = r & 15;
        int i  = ij >> 2;
        int j  = ij & 3;
        v = fea[(((size_t)b*32 + c)*(Hh*DSf) + h*DSf + i)*(Ww*DSf) + w*DSf + j];
    }
    g_x0[idx] = v;
}

// ---------------------------------------------------------------------------
// Kernel 2: 3x3 conv (zero pad 1) + BN(eval) + optional ReLU.
// Block: 256 threads. Tile = 16(H) x 32(W) spatial x 24 output channels.
// Thread: 2x4 spatial micro-tile x 6 ocs -> 24 packed f32x2 accumulators.
// Staging split: LDG(->regs) BEFORE compute, STS AFTER compute (latency hidden).
// Weight rows padded to 12 float2 (16B-aligned) -> fetched via LDS.128.
// grid = (64 spatial tiles, 6 oc chunks of 24, B)
// ---------------------------------------------------------------------------
#define TILE_H 16
#define TILE_W 32
#define HALO_H 18
#define HALO_W 34
#define SROW   36   // padded row (words): 144B rows keep 16B alignment
#define OCB    24   // output channels per block
#define OCT    6    // output channels per thread
#define WPAD   12   // padded weight row (float2) -> 96B, 16B-aligned per oc

template<int CIN, bool RELU>
__global__ __launch_bounds__(256, 2)
void conv3x3_bn(const float* __restrict__ in,    // [B, CIN, H, W]
                const float* __restrict__ wt,    // [144, CIN, 3, 3]
                const float* __restrict__ gam,   // [144]
                const float* __restrict__ bet,   // [144]
                float* __restrict__ out)         // [B, 144, H, W]
{
    __shared__ float s_in[2][HALO_H][SROW];
    __shared__ __align__(16) float2 s_wt[2][OCB][WPAD];  // (w,w) duplicated

    const int t    = threadIdx.x;
    const int tile = blockIdx.x;           // 8 tiles in W, 8 in H
    const int tx   = tile & 7;
    const int ty   = tile >> 3;
    const int ocb  = blockIdx.y * OCB;
    const int b    = blockIdx.z;

    const int ocg  = t >> 6;               // 0..3 -> ocs [ocg*6, ocg*6+5]
    const int sp   = t & 63;
    const int sy   = sp >> 3;              // 0..7 -> 2 rows each
    const int sx   = sp & 7;               // 0..7 -> 4 cols each
    const int py   = ty*TILE_H + sy*2;
    const int px   = tx*TILE_W + sx*4;

    const float* inb = in + (size_t)b * CIN * HWsz;
    const float* wtb = wt + (size_t)ocb * CIN * 9;

    // ---- hoisted staging descriptors (loop-invariant across ic)
    int  stg_soff[3];
    int  stg_goff[3];
    bool stg_val [3];
    const bool s2_act = (t < HALO_H*HALO_W - 512);
    {
        const int gy0 = ty*TILE_H - 1;
        const int gx0 = tx*TILE_W - 1;
#pragma unroll
        for (int s = 0; s < 3; s++) {
            int l = t + s*256;
            int ly = l / HALO_W, lx = l - ly*HALO_W;
            int gy = gy0 + ly,   gx = gx0 + lx;
            bool val = (s < 2 || s2_act) && gy >= 0 && gy < Hh && gx >= 0 && gx < Ww;
            stg_val[s]  = val;
            stg_soff[s] = ly*SROW + lx;
            stg_goff[s] = val ? (gy*Ww + gx) : 0;
        }
    }
    // weight staging indices (threads 0..215 cover 24 oc x 9 taps)
    const int  woo   = t / 9;
    const int  wkk   = t - woo*9;
    const bool wact  = (t < OCB*9);
    const float* wsrc = wtb + (size_t)woo*CIN*9 + wkk;

    // ---- pre-zero OOB halo cells once (never rewritten)
#pragma unroll
    for (int s = 0; s < 3; s++) {
        bool act = (s < 2) || s2_act;
        if (act && !stg_val[s]) {
            (&s_in[0][0][0])[stg_soff[s]] = 0.0f;
            (&s_in[1][0][0])[stg_soff[s]] = 0.0f;
        }
    }

    // acc[k][oy][oxp]: oxp=0 -> out cols (0,1), oxp=1 -> (2,3), packed f32x2
    ull acc[OCT][2][2];
#pragma unroll
    for (int k = 0; k < OCT; k++)
#pragma unroll
        for (int oy = 0; oy < 2; oy++) {
            acc[k][oy][0] = 0ull;
            acc[k][oy][1] = 0ull;
        }

    // prefetch registers carried across the compute block
    float pf0, pf1, pf2, pfw;

    // ---- staging: LDG phase (issue loads into regs; no smem writes)
    auto stage_load = [&](int ic) {
        const float* ip = inb + (size_t)ic * HWsz;
        pf0 = stg_val[0] ? __ldg(ip + stg_goff[0]) : 0.0f;
        pf1 = stg_val[1] ? __ldg(ip + stg_goff[1]) : 0.0f;
        pf2 = (s2_act && stg_val[2]) ? __ldg(ip + stg_goff[2]) : 0.0f;
        if (wact) pfw = __ldg(wsrc + (size_t)ic*9);
    };
    // ---- staging: STS phase (after compute; data long since arrived)
    auto stage_store = [&](int buf) {
        float* sb = &s_in[buf][0][0];
        if (stg_val[0]) sb[stg_soff[0]] = pf0;
        if (stg_val[1]) sb[stg_soff[1]] = pf1;
        if (stg_val[2]) sb[stg_soff[2]] = pf2;   // val implies s2_act
        if (wact) s_wt[buf][woo][wkk] = make_float2(pfw, pfw);
    };

    // ---- compute helper: accumulate from buffer `buf`
    auto compute = [&](int buf) {
        // p[r][0..4] = pairs (x0,x1)(x1,x2)(x2,x3)(x3,x4)(x4,x5)
        ull p[4][5];
#pragma unroll
        for (int r = 0; r < 4; r++) {
            const float* rp = &s_in[buf][sy*2 + r][sx*4];
            ull e0 = *(const ull*)(rp + 0);   // (x0,x1) 8B-aligned
            ull e1 = *(const ull*)(rp + 2);   // (x2,x3)
            ull e2 = *(const ull*)(rp + 4);   // (x4,x5)
            float2 f0 = f32x2_unpack(e0);
            float2 f1 = f32x2_unpack(e1);
            float2 f2 = f32x2_unpack(e2);
            p[r][0] = e0;
            p[r][1] = f32x2_pack(f0.y, f1.x);
            p[r][2] = e1;
            p[r][3] = f32x2_pack(f1.y, f2.x);
            p[r][4] = e2;
        }
#pragma unroll
        for (int k = 0; k < OCT; k++) {
            // 9 duplicated weights via 4x LDS.128 + 1x LDS.64 (broadcast)
            const ulonglong2* wp = (const ulonglong2*)&s_wt[buf][ocg*OCT + k][0];
            ull wv[9];
            {
                ulonglong2 q0 = wp[0], q1 = wp[1], q2 = wp[2], q3 = wp[3];
                wv[0]=q0.x; wv[1]=q0.y; wv[2]=q1.x; wv[3]=q1.y;
                wv[4]=q2.x; wv[5]=q2.y; wv[6]=q3.x; wv[7]=q3.y;
                wv[8]=*(const ull*)&s_wt[buf][ocg*OCT + k][8];
            }
#pragma unroll
            for (int oy = 0; oy < 2; oy++)
#pragma unroll
                for (int dy = 0; dy < 3; dy++) {
                    const int r = oy + dy;
#pragma unroll
                    for (int dx = 0; dx < 3; dx++) {
                        f32x2_fma(acc[k][oy][0], wv[dy*3+dx], p[r][dx]);
                        f32x2_fma(acc[k][oy][1], wv[dy*3+dx], p[r][dx+2]);
                    }
                }
        }
    };

    // ---- pipelined mainloop, ic unrolled by 2 (static buffer indices)
    stage_load(0);
    stage_store(0);
    __syncthreads();
#pragma unroll 1
    for (int ic = 0; ic < CIN; ic += 2) {
        if (ic + 1 < CIN) stage_load(ic + 1);   // LDG issued before compute
        compute(0);
        if (ic + 1 < CIN) stage_store(1);       // STS after compute (latency hidden)
        __syncthreads();
        if (ic + 1 < CIN) {
            if (ic + 2 < CIN) stage_load(ic + 2);
            compute(1);
            if (ic + 2 < CIN) stage_store(0);
            __syncthreads();
        }
    }

    // --- BN epilogue (+ReLU), vectorized store
    const float inv = rsqrtf(1.0f + 1e-5f);
#pragma unroll
    for (int k = 0; k < OCT; k++) {
        int oc = ocb + ocg*OCT + k;
        float sc = __ldg(gam + oc) * inv;
        float bb = __ldg(bet + oc);
#pragma unroll
        for (int oy = 0; oy < 2; oy++) {
            float2 a01 = f32x2_unpack(acc[k][oy][0]);
            float2 a23 = f32x2_unpack(acc[k][oy][1]);
            float4 v;
            v.x = a01.x * sc + bb;
            v.y = a01.y * sc + bb;
            v.z = a23.x * sc + bb;
            v.w = a23.y * sc + bb;
            if (RELU) {
                v.x = fmaxf(v.x, 0.0f); v.y = fmaxf(v.y, 0.0f);
                v.z = fmaxf(v.z, 0.0f); v.w = fmaxf(v.w, 0.0f);
            }
            *(float4*)(out + ((size_t)b*COUT + oc)*HWsz + (size_t)(py+oy)*Ww + px) = v;
        }
    }
}

// ---------------------------------------------------------------------------
// Kernel 3: per-(b,h,w): 16 softmaxes over 9 logits, blend 3x3 replication-
// padded disparity neighborhood, pixel-shuffle (x4), scale by DS=4.
// ---------------------------------------------------------------------------
__global__ void finalize_kernel(const float* __restrict__ x3,
                                const float* __restrict__ disp,
                                float* __restrict__ out) {
    int idx = blockIdx.x * blockDim.x + threadIdx.x;   // Bn*HWsz
    if (idx >= Bn*HWsz) return;
    int w = idx % Ww;
    int h = (idx / Ww) % Hh;
    int b = idx / HWsz;

    // 3x3 neighborhood with edge clamp (ReplicationPad2d(1))
    float nb[9];
#pragma unroll
    for (int dy = 0; dy < 3; dy++) {
        int hh = min(max(h + dy - 1, 0), Hh-1);
#pragma unroll
        for (int dx = 0; dx < 3; dx++) {
            int ww = min(max(w + dx - 1, 0), Ww-1);
            nb[dy*3+dx] = __ldg(disp + ((size_t)b*Hh + hh)*Ww + ww);
        }
    }

    const float* xp = x3 + (size_t)b*COUT*HWsz + (size_t)h*Ww + w;
    float* ob = out + (size_t)b*(Hh*DSf)*(Ww*DSf);

#pragma unroll
    for (int ds = 0; ds < 16; ds++) {
        float v[9];
        float mx = -3.4e38f;
#pragma unroll
        for (int k = 0; k < 9; k++) {
            v[k] = __ldg(xp + (size_t)(ds*9 + k)*HWsz);
            mx = fmaxf(mx, v[k]);
        }
        float se = 0.0f, r = 0.0f;
#pragma unroll
        for (int k = 0; k < 9; k++) {
            float e = expf(v[k] - mx);
            se += e;
            r = fmaf(e, nb[k], r);
        }
        r = r / se * (float)DSf;
        int i = ds >> 2, j = ds & 3;
        ob[(size_t)(h*DSf + i)*(Ww*DSf) + (size_t)w*DSf + j] = r;
    }
}

// ---------------------------------------------------------------------------
extern "C" void kernel_launch(void* const* d_in, const int* in_sizes, int n_in,
                              void* d_out, int out_size) {
    (void)in_sizes; (void)n_in; (void)out_size;
    const float* disp = (const float*)d_in[0];
    const float* fea  = (const float*)d_in[1];
    const float* w1   = (const float*)d_in[2];
    const float* g1   = (const float*)d_in[3];
    const float* b1   = (const float*)d_in[4];
    const float* w2   = (const float*)d_in[5];
    const float* g2   = (const float*)d_in[6];
    const float* b2   = (const float*)d_in[7];
    const float* w3   = (const float*)d_in[8];
    const float* g3   = (const float*)d_in[9];
    const float* b3   = (const float*)d_in[10];
    float* out = (float*)d_out;

    float *x0, *xa, *xb;
    cudaGetSymbolAddress((void**)&x0, g_x0);
    cudaGetSymbolAddress((void**)&xa, g_xa);
    cudaGetSymbolAddress((void**)&xb, g_xb);

    // 1) space-to-depth + concat
    {
        size_t n0 = (size_t)Bn*CIN1*HWsz;
        s2d_kernel<<<(unsigned)((n0 + 255)/256), 256>>>(disp, fea);
    }

    // 2) three convs (ping-pong xa/xb)
    dim3 grid(64, COUT/OCB, Bn);   // 64 spatial tiles, 6 oc chunks of 24, batch
    conv3x3_bn<CIN1, true ><<<grid, 256>>>(x0, w1, g1, b1, xa);
    conv3x3_bn<COUT, true ><<<grid, 256>>>(xa, w2, g2, b2, xb);
    conv3x3_bn<COUT, false><<<grid, 256>>>(xb, w3, g3, b3, xa);

    // 3) softmax + disparity blend + pixel shuffle
    finalize_kernel<<<(Bn*HWsz + 127)/128, 128>>>(xa, disp, out);
}

// round 15
// speedup vs baseline: 1.2029x; 1.0683x over previous
#include <cuda_runtime.h>
#include <math.h>

// Problem constants (fixed shapes from reference)
#define Hh   128
#define Ww   256
#define Bn   2
#define COUT 144
#define CIN1 513
#define DSf  4
#define HWsz (Hh*Ww)

// Scratch (device globals: allocation-free per harness rules)
__device__ float g_x0[(size_t)Bn*CIN1*HWsz];   // concat(disp, space_to_depth(fea))
__device__ float g_xa[(size_t)Bn*COUT*HWsz];   // ping
__device__ float g_xb[(size_t)Bn*COUT*HWsz];   // pong

typedef unsigned long long ull;

// ---- packed f32x2 helpers (sm_100+ PTX; SASS FFMA2) -----------------------
__device__ __forceinline__ ull f32x2_pack(float lo, float hi) {
    ull r;
    asm("mov.b64 %0, {%1, %2};" : "=l"(r) : "f"(lo), "f"(hi));
    return r;
}
__device__ __forceinline__ void f32x2_fma(ull& d, ull a, ull b) {
    asm("fma.rn.f32x2 %0, %1, %2, %0;" : "+l"(d) : "l"(a), "l"(b));
}
__device__ __forceinline__ float2 f32x2_unpack(ull v) {
    float2 f;
    asm("mov.b64 {%0, %1}, %2;" : "=f"(f.x), "=f"(f.y) : "l"(v));
    return f;
}

// ---------------------------------------------------------------------------
// Kernel 1: build x0[b, ci, h, w]
// ---------------------------------------------------------------------------
__global__ void s2d_kernel(const float* __restrict__ disp,
                           const float* __restrict__ fea) {
    size_t idx = (size_t)blockIdx.x * blockDim.x + threadIdx.x;
    size_t total = (size_t)Bn * CIN1 * HWsz;
    if (idx >= total) return;
    int w  = (int)(idx % Ww);
    int h  = (int)((idx / Ww) % Hh);
    int ci = (int)((idx / HWsz) % CIN1);
    int b  = (int)(idx / ((size_t)HWsz * CIN1));
    float v;
    if (ci == 0) {
        v = disp[((size_t)b*Hh + h)*Ww + w];
    } else {
        int r  = ci - 1;
        int c  = r >> 4;
        int ij = r & 15;
        int i  = ij >> 2;
        int j  = ij & 3;
        v = fea[(((size_t)b*32 + c)*(Hh*DSf) + h*DSf + i)*(Ww*DSf) + w*DSf + j];
    }
    g_x0[idx] = v;
}

// ---------------------------------------------------------------------------
// Kernel 2: 3x3 conv (zero pad 1) + BN(eval) + optional ReLU.
// Block: 256 threads. Tile = 16(H) x 32(W) spatial x 24 output channels.
// Thread: 2x4 spatial micro-tile x 6 ocs -> 24 packed f32x2 accumulators.
// TWO input planes per barrier phase: 432 FFMA2 between syncs, half the
// barriers. LDG before compute, STS between the two plane-computes.
// Input rows fetched via LDS.128 + LDS.64 (8 loads/plane).
// grid = (64 spatial tiles, 6 oc chunks of 24, B)
// ---------------------------------------------------------------------------
#define TILE_H 16
#define TILE_W 32
#define HALO_H 18
#define HALO_W 34
#define SROW   36   // padded row (words)
#define OCB    24   // output channels per block
#define OCT    6    // output channels per thread
#define WPAD   12   // padded weight row (float2) -> 96B, 16B-aligned per oc

template<int CIN, bool RELU>
__global__ __launch_bounds__(256, 2)
void conv3x3_bn(const float* __restrict__ in,    // [B, CIN, H, W]
                const float* __restrict__ wt,    // [144, CIN, 3, 3]
                const float* __restrict__ gam,   // [144]
                const float* __restrict__ bet,   // [144]
                float* __restrict__ out)         // [B, 144, H, W]
{
    __shared__ float s_in[2][2][HALO_H][SROW];                 // [buf][plane]
    __shared__ __align__(16) float2 s_wt[2][2][OCB][WPAD];     // (w,w) dup

    const int t    = threadIdx.x;
    const int tile = blockIdx.x;           // 8 tiles in W, 8 in H
    const int tx   = tile & 7;
    const int ty   = tile >> 3;
    const int ocb  = blockIdx.y * OCB;
    const int b    = blockIdx.z;

    const int ocg  = t >> 6;               // 0..3 -> ocs [ocg*6, ocg*6+5]
    const int sp   = t & 63;
    const int sy   = sp >> 3;              // 0..7 -> 2 rows each
    const int sx   = sp & 7;               // 0..7 -> 4 cols each
    const int py   = ty*TILE_H + sy*2;
    const int px   = tx*TILE_W + sx*4;

    const float* inb = in + (size_t)b * CIN * HWsz;
    const float* wtb = wt + (size_t)ocb * CIN * 9;

    // ---- hoisted staging descriptors (loop-invariant)
    int  stg_soff[3];
    int  stg_goff[3];
    bool stg_val [3];
    const bool s2_act = (t < HALO_H*HALO_W - 512);
    {
        const int gy0 = ty*TILE_H - 1;
        const int gx0 = tx*TILE_W - 1;
#pragma unroll
        for (int s = 0; s < 3; s++) {
            int l = t + s*256;
            int ly = l / HALO_W, lx = l - ly*HALO_W;
            int gy = gy0 + ly,   gx = gx0 + lx;
            bool val = (s < 2 || s2_act) && gy >= 0 && gy < Hh && gx >= 0 && gx < Ww;
            stg_val[s]  = val;
            stg_soff[s] = ly*SROW + lx;
            stg_goff[s] = val ? (gy*Ww + gx) : 0;
        }
    }
    // weight staging indices (threads 0..215 cover 24 oc x 9 taps)
    const int  woo   = t / 9;
    const int  wkk   = t - woo*9;
    const bool wact  = (t < OCB*9);
    const float* wsrc = wtb + (size_t)woo*CIN*9 + wkk;

    // ---- pre-zero OOB halo cells once (never rewritten)
#pragma unroll
    for (int s = 0; s < 3; s++) {
        bool act = (s < 2) || s2_act;
        if (act && !stg_val[s]) {
#pragma unroll
            for (int bb2 = 0; bb2 < 2; bb2++)
#pragma unroll
                for (int pl = 0; pl < 2; pl++)
                    (&s_in[bb2][pl][0][0])[stg_soff[s]] = 0.0f;
        }
    }

    // acc[k][oy][oxp], packed f32x2
    ull acc[OCT][2][2];
#pragma unroll
    for (int k = 0; k < OCT; k++)
#pragma unroll
        for (int oy = 0; oy < 2; oy++) {
            acc[k][oy][0] = 0ull;
            acc[k][oy][1] = 0ull;
        }

    // prefetch registers for a PAIR of planes
    float pf[6];
    float pfw0, pfw1;

    const int NP = (CIN + 1) / 2;   // number of plane pairs

    // ---- staging: LDG phase for pair `pr` (planes 2pr, 2pr+1)
    auto stage_load = [&](int pr) {
        int ic0 = 2*pr;
        int ic1 = 2*pr + 1;
        int ic1c = (ic1 < CIN) ? ic1 : (CIN - 1);   // clamp: no OOB reads
        const float* ip0 = inb + (size_t)ic0  * HWsz;
        const float* ip1 = inb + (size_t)ic1c * HWsz;
        pf[0] = stg_val[0] ? __ldg(ip0 + stg_goff[0]) : 0.0f;
        pf[1] = stg_val[1] ? __ldg(ip0 + stg_goff[1]) : 0.0f;
        pf[2] = (s2_act && stg_val[2]) ? __ldg(ip0 + stg_goff[2]) : 0.0f;
        pf[3] = stg_val[0] ? __ldg(ip1 + stg_goff[0]) : 0.0f;
        pf[4] = stg_val[1] ? __ldg(ip1 + stg_goff[1]) : 0.0f;
        pf[5] = (s2_act && stg_val[2]) ? __ldg(ip1 + stg_goff[2]) : 0.0f;
        if (wact) {
            pfw0 = __ldg(wsrc + (size_t)ic0*9);
            pfw1 = (ic1 < CIN) ? __ldg(wsrc + (size_t)ic1*9) : 0.0f;  // tail: zero weight
        }
    };
    // ---- staging: STS phase (between the two plane-computes)
    auto stage_store = [&](int buf) {
        float* sb0 = &s_in[buf][0][0][0];
        float* sb1 = &s_in[buf][1][0][0];
        if (stg_val[0]) { sb0[stg_soff[0]] = pf[0]; sb1[stg_soff[0]] = pf[3]; }
        if (stg_val[1]) { sb0[stg_soff[1]] = pf[1]; sb1[stg_soff[1]] = pf[4]; }
        if (stg_val[2]) { sb0[stg_soff[2]] = pf[2]; sb1[stg_soff[2]] = pf[5]; }
        if (wact) {
            s_wt[buf][0][woo][wkk] = make_float2(pfw0, pfw0);
            s_wt[buf][1][woo][wkk] = make_float2(pfw1, pfw1);
        }
    };

    // ---- compute: accumulate one plane from buffer `buf`
    auto compute = [&](int buf, int pl) {
        // p[r][0..4] = pairs (x0,x1)(x1,x2)(x2,x3)(x3,x4)(x4,x5)
        ull p[4][5];
#pragma unroll
        for (int r = 0; r < 4; r++) {
            const float* rp = &s_in[buf][pl][sy*2 + r][sx*4];
            float4 v4 = *(const float4*)rp;        // LDS.128: x0..x3 (16B-aligned)
            ull   e2 = *(const ull*)(rp + 4);      // LDS.64:  (x4,x5)
            float2 f2 = f32x2_unpack(e2);
            p[r][0] = f32x2_pack(v4.x, v4.y);
            p[r][1] = f32x2_pack(v4.y, v4.z);
            p[r][2] = f32x2_pack(v4.z, v4.w);
            p[r][3] = f32x2_pack(v4.w, f2.x);
            p[r][4] = e2;
        }
#pragma unroll
        for (int k = 0; k < OCT; k++) {
            const ulonglong2* wp = (const ulonglong2*)&s_wt[buf][pl][ocg*OCT + k][0];
            ull wv[9];
            {
                ulonglong2 q0 = wp[0], q1 = wp[1], q2 = wp[2], q3 = wp[3];
                wv[0]=q0.x; wv[1]=q0.y; wv[2]=q1.x; wv[3]=q1.y;
                wv[4]=q2.x; wv[5]=q2.y; wv[6]=q3.x; wv[7]=q3.y;
                wv[8]=*(const ull*)&s_wt[buf][pl][ocg*OCT + k][8];
            }
#pragma unroll
            for (int oy = 0; oy < 2; oy++)
#pragma unroll
                for (int dy = 0; dy < 3; dy++) {
                    const int r = oy + dy;
#pragma unroll
                    for (int dx = 0; dx < 3; dx++) {
                        f32x2_fma(acc[k][oy][0], wv[dy*3+dx], p[r][dx]);
                        f32x2_fma(acc[k][oy][1], wv[dy*3+dx], p[r][dx+2]);
                    }
                }
        }
    };

    // ---- pipelined mainloop over plane PAIRS, unrolled by 2 (static buf idx)
    stage_load(0);
    stage_store(0);
    __syncthreads();
#pragma unroll 1
    for (int pr = 0; pr < NP; pr += 2) {
        if (pr + 1 < NP) stage_load(pr + 1);
        compute(0, 0);
        if (pr + 1 < NP) stage_store(1);    // STS overlaps second plane-compute
        compute(0, 1);
        __syncthreads();
        if (pr + 1 < NP) {
            if (pr + 2 < NP) stage_load(pr + 2);
            compute(1, 0);
            if (pr + 2 < NP) stage_store(0);
            compute(1, 1);
            __syncthreads();
        }
    }

    // --- BN epilogue (+ReLU), vectorized store
    const float inv = rsqrtf(1.0f + 1e-5f);
#pragma unroll
    for (int k = 0; k < OCT; k++) {
        int oc = ocb + ocg*OCT + k;
        float sc = __ldg(gam + oc) * inv;
        float bb = __ldg(bet + oc);
#pragma unroll
        for (int oy = 0; oy < 2; oy++) {
            float2 a01 = f32x2_unpack(acc[k][oy][0]);
            float2 a23 = f32x2_unpack(acc[k][oy][1]);
            float4 v;
            v.x = a01.x * sc + bb;
            v.y = a01.y * sc + bb;
            v.z = a23.x * sc + bb;
            v.w = a23.y * sc + bb;
            if (RELU) {
                v.x = fmaxf(v.x, 0.0f); v.y = fmaxf(v.y, 0.0f);
                v.z = fmaxf(v.z, 0.0f); v.w = fmaxf(v.w, 0.0f);
            }
            *(float4*)(out + ((size_t)b*COUT + oc)*HWsz + (size_t)(py+oy)*Ww + px) = v;
        }
    }
}

// ---------------------------------------------------------------------------
// Kernel 3: softmax + disparity blend + pixel shuffle
// ---------------------------------------------------------------------------
__global__ void finalize_kernel(const float* __restrict__ x3,
                                const float* __restrict__ disp,
                                float* __restrict__ out) {
    int idx = blockIdx.x * blockDim.x + threadIdx.x;   // Bn*HWsz
    if (idx >= Bn*HWsz) return;
    int w = idx % Ww;
    int h = (idx / Ww) % Hh;
    int b = idx / HWsz;

    float nb[9];
#pragma unroll
    for (int dy = 0; dy < 3; dy++) {
        int hh = min(max(h + dy - 1, 0), Hh-1);
#pragma unroll
        for (int dx = 0; dx < 3; dx++) {
            int ww = min(max(w + dx - 1, 0), Ww-1);
            nb[dy*3+dx] = __ldg(disp + ((size_t)b*Hh + hh)*Ww + ww);
        }
    }

    const float* xp = x3 + (size_t)b*COUT*HWsz + (size_t)h*Ww + w;
    float* ob = out + (size_t)b*(Hh*DSf)*(Ww*DSf);

#pragma unroll
    for (int ds = 0; ds < 16; ds++) {
        float v[9];
        float mx = -3.4e38f;
#pragma unroll
        for (int k = 0; k < 9; k++) {
            v[k] = __ldg(xp + (size_t)(ds*9 + k)*HWsz);
            mx = fmaxf(mx, v[k]);
        }
        float se = 0.0f, r = 0.0f;
#pragma unroll
        for (int k = 0; k < 9; k++) {
            float e = expf(v[k] - mx);
            se += e;
            r = fmaf(e, nb[k], r);
        }
        r = r / se * (float)DSf;
        int i = ds >> 2, j = ds & 3;
        ob[(size_t)(h*DSf + i)*(Ww*DSf) + (size_t)w*DSf + j] = r;
    }
}

// ---------------------------------------------------------------------------
extern "C" void kernel_launch(void* const* d_in, const int* in_sizes, int n_in,
                              void* d_out, int out_size) {
    (void)in_sizes; (void)n_in; (void)out_size;
    const float* disp = (const float*)d_in[0];
    const float* fea  = (const float*)d_in[1];
    const float* w1   = (const float*)d_in[2];
    const float* g1   = (const float*)d_in[3];
    const float* b1   = (const float*)d_in[4];
    const float* w2   = (const float*)d_in[5];
    const float* g2   = (const float*)d_in[6];
    const float* b2   = (const float*)d_in[7];
    const float* w3   = (const float*)d_in[8];
    const float* g3   = (const float*)d_in[9];
    const float* b3   = (const float*)d_in[10];
    float* out = (float*)d_out;

    float *x0, *xa, *xb;
    cudaGetSymbolAddress((void**)&x0, g_x0);
    cudaGetSymbolAddress((void**)&xa, g_xa);
    cudaGetSymbolAddress((void**)&xb, g_xb);

    // 1) space-to-depth + concat
    {
        size_t n0 = (size_t)Bn*CIN1*HWsz;
        s2d_kernel<<<(unsigned)((n0 + 255)/256), 256>>>(disp, fea);
    }

    // 2) three convs (ping-pong xa/xb)
    dim3 grid(64, COUT/OCB, Bn);   // 64 spatial tiles, 6 oc chunks of 24, batch
    conv3x3_bn<CIN1, true ><<<grid, 256>>>(x0, w1, g1, b1, xa);
    conv3x3_bn<COUT, true ><<<grid, 256>>>(xa, w2, g2, b2, xb);
    conv3x3_bn<COUT, false><<<grid, 256>>>(xb, w3, g3, b3, xa);

    // 3) softmax + disparity blend + pixel shuffle
    finalize_kernel<<<(Bn*HWsz + 127)/128, 128>>>(xa, disp, out);
}